// round 2
// baseline (speedup 1.0000x reference)
#include <cuda_runtime.h>
#include <cuda_bf16.h>

// ---------------------------------------------------------------------------
// out[m] = sum_n I_n * exp(-0.5 * (x_m)^T A_n x_m - 2 b_n.x_m + c_n)
// Folded: t = K*(x^T A x - 2 b.x + c) + log2(I),  K = -0.5*log2(e)
//         out[m] = sum_n exp2(t)
// Coefficients per gaussian (10): K*a00, K*a11, K*a22, 2K*a01, 2K*a02, 2K*a12,
//                                 -2K*bx, -2K*by, -2K*bz, K*c + log2(I)
// Stored PRE-SPLATTED as f32x2 pairs (80 bytes / gaussian) so the inner loop
// feeds fma.rn.f32x2 directly from LDS.128 loads with no MOV splats.
// ---------------------------------------------------------------------------

#define NG_MAX 8192
__device__ __align__(16) float g_coef[NG_MAX * 20];

#define CHUNK 256          // gaussians per CTA chunk (20 KB smem)
#define PTS_PER_CTA 1024   // 256 threads * 4 points

// ---- f32x2 packed helpers (Blackwell FFMA2 path, PTX-only) ----------------
__device__ __forceinline__ unsigned long long fma2(unsigned long long a,
                                                   unsigned long long b,
                                                   unsigned long long c) {
    unsigned long long d;
    asm("fma.rn.f32x2 %0, %1, %2, %3;" : "=l"(d) : "l"(a), "l"(b), "l"(c));
    return d;
}
__device__ __forceinline__ unsigned long long add2(unsigned long long a,
                                                   unsigned long long b) {
    unsigned long long d;
    asm("add.rn.f32x2 %0, %1, %2;" : "=l"(d) : "l"(a), "l"(b));
    return d;
}
__device__ __forceinline__ unsigned long long mul2(unsigned long long a,
                                                   unsigned long long b) {
    unsigned long long d;
    asm("mul.rn.f32x2 %0, %1, %2;" : "=l"(d) : "l"(a), "l"(b));
    return d;
}
__device__ __forceinline__ unsigned long long pk2(float lo, float hi) {
    unsigned long long r;
    asm("mov.b64 %0, {%1, %2};" : "=l"(r) : "f"(lo), "f"(hi));
    return r;
}
__device__ __forceinline__ void upk2(unsigned long long v, float& lo, float& hi) {
    asm("mov.b64 {%0, %1}, %2;" : "=f"(lo), "=f"(hi) : "l"(v));
}
__device__ __forceinline__ float ex2(float x) {
    float y;
    asm("ex2.approx.ftz.f32 %0, %1;" : "=f"(y) : "f"(x));
    return y;
}

// ---------------------------------------------------------------------------
// Prep: per-gaussian coefficient computation (trivial cost, 4096 threads)
// ---------------------------------------------------------------------------
__global__ void prep_kernel(const float* __restrict__ positions,
                            const float* __restrict__ scales,
                            const float* __restrict__ rotations,
                            const float* __restrict__ intensities,
                            int n) {
    int g = blockIdx.x * blockDim.x + threadIdx.x;
    if (g >= n || g >= NG_MAX) return;

    float qw = rotations[4 * g + 0];
    float qx = rotations[4 * g + 1];
    float qy = rotations[4 * g + 2];
    float qz = rotations[4 * g + 3];
    float nrm = sqrtf(qw * qw + qx * qx + qy * qy + qz * qz);
    float inv = 1.0f / (nrm + 1e-8f);
    qw *= inv; qx *= inv; qy *= inv; qz *= inv;

    float r00 = 1.0f - 2.0f * (qy * qy + qz * qz);
    float r01 = 2.0f * (qx * qy - qz * qw);
    float r02 = 2.0f * (qx * qz + qy * qw);
    float r10 = 2.0f * (qx * qy + qz * qw);
    float r11 = 1.0f - 2.0f * (qx * qx + qz * qz);
    float r12 = 2.0f * (qy * qz - qx * qw);
    float r20 = 2.0f * (qx * qz - qy * qw);
    float r21 = 2.0f * (qy * qz + qx * qw);
    float r22 = 1.0f - 2.0f * (qx * qx + qy * qy);

    float s0 = fabsf(scales[3 * g + 0]) + 1e-6f;
    float s1 = fabsf(scales[3 * g + 1]) + 1e-6f;
    float s2 = fabsf(scales[3 * g + 2]) + 1e-6f;
    float i0 = 1.0f / (s0 * s0);
    float i1 = 1.0f / (s1 * s1);
    float i2 = 1.0f / (s2 * s2);

    // A = R diag(i) R^T (symmetric)
    float a00 = r00 * r00 * i0 + r01 * r01 * i1 + r02 * r02 * i2;
    float a01 = r00 * r10 * i0 + r01 * r11 * i1 + r02 * r12 * i2;
    float a02 = r00 * r20 * i0 + r01 * r21 * i1 + r02 * r22 * i2;
    float a11 = r10 * r10 * i0 + r11 * r11 * i1 + r12 * r12 * i2;
    float a12 = r10 * r20 * i0 + r11 * r21 * i1 + r12 * r22 * i2;
    float a22 = r20 * r20 * i0 + r21 * r21 * i1 + r22 * r22 * i2;

    float px = positions[3 * g + 0];
    float py = positions[3 * g + 1];
    float pz = positions[3 * g + 2];
    float bx = a00 * px + a01 * py + a02 * pz;
    float by = a01 * px + a11 * py + a12 * pz;
    float bz = a02 * px + a12 * py + a22 * pz;
    float c  = bx * px + by * py + bz * pz;

    const float K = -0.72134752044448169f;  // -0.5 * log2(e)
    float cf = K * c + log2f(intensities[g]);

    float v[10];
    v[0] = K * a00;
    v[1] = K * a11;
    v[2] = K * a22;
    v[3] = 2.0f * K * a01;
    v[4] = 2.0f * K * a02;
    v[5] = 2.0f * K * a12;
    v[6] = -2.0f * K * bx;
    v[7] = -2.0f * K * by;
    v[8] = -2.0f * K * bz;
    v[9] = cf;

#pragma unroll
    for (int k = 0; k < 10; k++) {
        g_coef[g * 20 + 2 * k + 0] = v[k];
        g_coef[g * 20 + 2 * k + 1] = v[k];
    }
}

// ---------------------------------------------------------------------------
// Main: each CTA = 1024 points x CHUNK gaussians; 4 points/thread as 2 f32x2
// lanes; gaussian records broadcast from shared memory via LDS.128.
// ---------------------------------------------------------------------------
__global__ void __launch_bounds__(256)
gauss_kernel(const float* __restrict__ pts, float* __restrict__ out,
             int M, int n_gauss) {
    __shared__ __align__(16) float sm[CHUNK * 20];

    const int tid   = threadIdx.x;
    const int pbase = blockIdx.x * PTS_PER_CTA;
    const int gbase = blockIdx.y * CHUNK;

    // --- stage gaussian chunk into smem (pad tail with cf = -inf -> exp2=0)
    {
        ulonglong2* dst = (ulonglong2*)sm;
        for (int i = tid; i < CHUNK * 5; i += 256) {
            int grec = gbase + i / 5;
            ulonglong2 v;
            if (grec < n_gauss) {
                v = ((const ulonglong2*)(g_coef + (size_t)grec * 20))[i % 5];
            } else {
                v.x = 0ull;
                v.y = (i % 5 == 4) ? 0xff800000ff800000ull : 0ull;  // (-inf,-inf)
            }
            dst[i] = v;
        }
    }

    // --- load 4 points, precompute products, pack to f32x2
    float x[4], y[4], z[4];
#pragma unroll
    for (int j = 0; j < 4; j++) {
        int p = pbase + tid + j * 256;
        bool ok = (p < M);
        x[j] = ok ? pts[3 * p + 0] : 0.0f;
        y[j] = ok ? pts[3 * p + 1] : 0.0f;
        z[j] = ok ? pts[3 * p + 2] : 0.0f;
    }
    unsigned long long xA = pk2(x[0], x[1]), xB = pk2(x[2], x[3]);
    unsigned long long yA = pk2(y[0], y[1]), yB = pk2(y[2], y[3]);
    unsigned long long zA = pk2(z[0], z[1]), zB = pk2(z[2], z[3]);
    unsigned long long xxA = mul2(xA, xA), xxB = mul2(xB, xB);
    unsigned long long yyA = mul2(yA, yA), yyB = mul2(yB, yB);
    unsigned long long zzA = mul2(zA, zA), zzB = mul2(zB, zB);
    unsigned long long xyA = mul2(xA, yA), xyB = mul2(xB, yB);
    unsigned long long xzA = mul2(xA, zA), xzB = mul2(xB, zB);
    unsigned long long yzA = mul2(yA, zA), yzB = mul2(yB, zB);

    unsigned long long accA = 0ull, accB = 0ull;  // (0.0f, 0.0f)

    __syncthreads();

    const ulonglong2* recs = (const ulonglong2*)sm;
#pragma unroll 2
    for (int g = 0; g < CHUNK; ++g) {
        ulonglong2 q0 = recs[g * 5 + 0];  // Ka00 | Ka11
        ulonglong2 q1 = recs[g * 5 + 1];  // Ka22 | 2Ka01
        ulonglong2 q2 = recs[g * 5 + 2];  // 2Ka02 | 2Ka12
        ulonglong2 q3 = recs[g * 5 + 3];  // bx | by
        ulonglong2 q4 = recs[g * 5 + 4];  // bz | cf

        unsigned long long tA = fma2(q0.x, xxA, q4.y);
        unsigned long long tB = fma2(q0.x, xxB, q4.y);
        tA = fma2(q0.y, yyA, tA);  tB = fma2(q0.y, yyB, tB);
        tA = fma2(q1.x, zzA, tA);  tB = fma2(q1.x, zzB, tB);
        tA = fma2(q1.y, xyA, tA);  tB = fma2(q1.y, xyB, tB);
        tA = fma2(q2.x, xzA, tA);  tB = fma2(q2.x, xzB, tB);
        tA = fma2(q2.y, yzA, tA);  tB = fma2(q2.y, yzB, tB);
        tA = fma2(q3.x, xA,  tA);  tB = fma2(q3.x, xB,  tB);
        tA = fma2(q3.y, yA,  tA);  tB = fma2(q3.y, yB,  tB);
        tA = fma2(q4.x, zA,  tA);  tB = fma2(q4.x, zB,  tB);

        float t0, t1, t2, t3;
        upk2(tA, t0, t1);
        upk2(tB, t2, t3);
        float e0 = ex2(t0), e1 = ex2(t1), e2 = ex2(t2), e3 = ex2(t3);
        accA = add2(accA, pk2(e0, e1));
        accB = add2(accB, pk2(e2, e3));
    }

    float a0, a1, a2, a3;
    upk2(accA, a0, a1);
    upk2(accB, a2, a3);
    int p0 = pbase + tid;
    if (p0 < M)        atomicAdd(out + p0, a0);
    if (p0 + 256 < M)  atomicAdd(out + p0 + 256, a1);
    if (p0 + 512 < M)  atomicAdd(out + p0 + 512, a2);
    if (p0 + 768 < M)  atomicAdd(out + p0 + 768, a3);
}

// ---------------------------------------------------------------------------
extern "C" void kernel_launch(void* const* d_in, const int* in_sizes, int n_in,
                              void* d_out, int out_size) {
    const float* sample_points = (const float*)d_in[0];
    const float* positions     = (const float*)d_in[1];
    const float* scales        = (const float*)d_in[2];
    const float* rotations     = (const float*)d_in[3];
    const float* intensities   = (const float*)d_in[4];
    float* out = (float*)d_out;

    int M = in_sizes[0] / 3;
    int n = in_sizes[4];

    cudaMemsetAsync(out, 0, (size_t)out_size * sizeof(float));

    prep_kernel<<<(n + 255) / 256, 256>>>(positions, scales, rotations,
                                          intensities, n);

    int PB = (M + PTS_PER_CTA - 1) / PTS_PER_CTA;
    int GC = (n + CHUNK - 1) / CHUNK;
    dim3 grid(PB, GC);
    gauss_kernel<<<grid, 256>>>(sample_points, out, M, n);
}